// round 1
// baseline (speedup 1.0000x reference)
#include <cuda_runtime.h>

#define DOUT 128
#define N_MAX 50000
#define E_MAX 800000

// Scratch (device globals — no allocation allowed)
__device__ float    g_z[(size_t)N_MAX * DOUT];
__device__ float    g_ssrc[N_MAX];
__device__ float    g_sdst[N_MAX];
__device__ float    g_e[E_MAX];
__device__ unsigned g_menc[N_MAX];
__device__ float    g_denom[N_MAX];

// ---------------------------------------------------------------------------
// Clear scratch + output (graph-replayed every launch)
// ---------------------------------------------------------------------------
__global__ void clear_kernel(float* __restrict__ out, int N) {
    int i = blockIdx.x * blockDim.x + threadIdx.x;
    int total = N * DOUT;
    if (i < total) out[i] = 0.0f;
    if (i < N) {
        g_denom[i] = 0.0f;
        g_menc[i]  = 0u;   // below encoding of -inf; only read for nodes with edges
    }
}

// ---------------------------------------------------------------------------
// z = h @ W  (smem-tiled fp32), plus s_src = z@a_l, s_dst = z@a_r
// Block: 256 threads = 8 warps. Each warp: 8 rows x 128 cols (lane owns 4 cols).
// smem: W (64KB) + h tile 64 rows (32KB) = 96KB dynamic.
// ---------------------------------------------------------------------------
__global__ void __launch_bounds__(256, 2)
gemm_kernel(const float* __restrict__ h, const float* __restrict__ W,
            const float* __restrict__ attn, int N) {
    extern __shared__ float smem[];
    float* Ws = smem;                 // [128][128]
    float* hs = smem + DOUT * DOUT;   // [64][128]

    int tid = threadIdx.x;
    const float4* W4 = (const float4*)W;
    float4* Ws4 = (float4*)Ws;
#pragma unroll
    for (int i = 0; i < 16; i++)          // 4096 float4
        Ws4[tid + i * 256] = W4[tid + i * 256];

    int rowbase = blockIdx.x * 64;
    float4* hs4 = (float4*)hs;
    const float4* h4 = (const float4*)h;
#pragma unroll
    for (int i = 0; i < 8; i++) {         // 2048 float4
        int idx = tid + i * 256;
        int r = idx >> 5;
        int c = idx & 31;
        float4 v = make_float4(0.f, 0.f, 0.f, 0.f);
        if (rowbase + r < N) v = h4[(size_t)(rowbase + r) * 32 + c];
        hs4[idx] = v;
    }
    __syncthreads();

    int warp = tid >> 5, lane = tid & 31;
    int r0 = warp * 8;                    // tile-local row base for this warp

    float4 acc[8];
#pragma unroll
    for (int r = 0; r < 8; r++) acc[r] = make_float4(0.f, 0.f, 0.f, 0.f);

#pragma unroll 4
    for (int k = 0; k < DOUT; k++) {
        float4 wk = Ws4[k * 32 + lane];   // 4 contiguous cols per lane
#pragma unroll
        for (int r = 0; r < 8; r++) {
            float hv = hs[(r0 + r) * DOUT + k];  // warp broadcast
            acc[r].x += hv * wk.x;
            acc[r].y += hv * wk.y;
            acc[r].z += hv * wk.z;
            acc[r].w += hv * wk.w;
        }
    }

    float4 al = ((const float4*)attn)[lane];        // a_l cols 4l..4l+3
    float4 ar = ((const float4*)attn)[32 + lane];   // a_r cols 4l..4l+3
    float4* z4 = (float4*)g_z;
#pragma unroll
    for (int r = 0; r < 8; r++) {
        int row = rowbase + r0 + r;
        if (row >= N) break;
        z4[(size_t)row * 32 + lane] = acc[r];
        float ps = acc[r].x * al.x + acc[r].y * al.y + acc[r].z * al.z + acc[r].w * al.w;
        float pd = acc[r].x * ar.x + acc[r].y * ar.y + acc[r].z * ar.z + acc[r].w * ar.w;
#pragma unroll
        for (int o = 16; o > 0; o >>= 1) {
            ps += __shfl_xor_sync(0xffffffffu, ps, o);
            pd += __shfl_xor_sync(0xffffffffu, pd, o);
        }
        if (lane == 0) { g_ssrc[row] = ps; g_sdst[row] = pd; }
    }
}

// ---------------------------------------------------------------------------
// Per-edge leaky-relu score + segment max via order-preserving uint atomicMax
// ---------------------------------------------------------------------------
__device__ __forceinline__ unsigned enc_f32(float f) {
    unsigned u = __float_as_uint(f);
    return (u & 0x80000000u) ? ~u : (u | 0x80000000u);
}
__device__ __forceinline__ float dec_f32(unsigned u) {
    return (u & 0x80000000u) ? __uint_as_float(u ^ 0x80000000u)
                             : __uint_as_float(~u);
}

__global__ void edge_pre(const int* __restrict__ src, const int* __restrict__ dst, int E) {
    int i = blockIdx.x * blockDim.x + threadIdx.x;
    if (i >= E) return;
    int s = src[i], d = dst[i];
    float v = g_ssrc[s] + g_sdst[d];
    float e = v > 0.0f ? v : 0.01f * v;   // leaky_relu slope 0.01
    g_e[i] = e;
    atomicMax(&g_menc[d], enc_f32(e));
}

// ---------------------------------------------------------------------------
// Fused: ex = exp(e - m[dst]); denom[dst] += ex;
//        out_un[dst] += (rel[etype] * ex) * z[src]     (denom divides later)
// One warp per edge; lane owns 4 cols as float4; vector atomics.
// ---------------------------------------------------------------------------
__global__ void edge_accum(const int* __restrict__ src, const int* __restrict__ dst,
                           const int* __restrict__ etype, const float* __restrict__ rel,
                           float* __restrict__ out, int E) {
    int gt = blockIdx.x * blockDim.x + threadIdx.x;
    int edge = gt >> 5;
    int lane = gt & 31;
    if (edge >= E) return;

    int s = src[edge], d = dst[edge], et = etype[edge];
    float m  = dec_f32(g_menc[d]);
    float ex = __expf(g_e[edge] - m);
    if (lane == 0) atomicAdd(&g_denom[d], ex);

    float rv  = (et == 0) ? 0.0f : rel[et];   // padding_idx=0 -> zero row
    float wgt = rv * ex;

    const float4* z4 = (const float4*)g_z;
    float4 zv = z4[(size_t)s * 32 + lane];
    float4 add = make_float4(wgt * zv.x, wgt * zv.y, wgt * zv.z, wgt * zv.w);
    atomicAdd((float4*)(out + (size_t)d * DOUT + (lane << 2)), add);
}

// ---------------------------------------------------------------------------
// out[n] /= denom[n]  (0 if node has no incoming edges)
// ---------------------------------------------------------------------------
__global__ void finalize(float* __restrict__ out, int N) {
    int i = blockIdx.x * blockDim.x + threadIdx.x;  // over N*32 float4
    if (i >= N * 32) return;
    int node = i >> 5;
    float dsum = g_denom[node];
    float inv = dsum > 0.0f ? __frcp_rn(dsum) : 0.0f;
    float4* o4 = (float4*)out;
    float4 v = o4[i];
    v.x *= inv; v.y *= inv; v.z *= inv; v.w *= inv;
    o4[i] = v;
}

// ---------------------------------------------------------------------------
extern "C" void kernel_launch(void* const* d_in, const int* in_sizes, int n_in,
                              void* d_out, int out_size) {
    const float* h    = (const float*)d_in[0];
    const float* W    = (const float*)d_in[1];
    const float* attn = (const float*)d_in[2];
    const float* rel  = (const float*)d_in[3];
    const int*   src  = (const int*)d_in[4];
    const int*   dst  = (const int*)d_in[5];
    const int*   et   = (const int*)d_in[6];
    float* out = (float*)d_out;

    int N = in_sizes[0] / DOUT;
    int E = in_sizes[4];

    int tot = N * DOUT;
    clear_kernel<<<(tot + 255) / 256, 256>>>(out, N);

    cudaFuncSetAttribute(gemm_kernel, cudaFuncAttributeMaxDynamicSharedMemorySize, 96 * 1024);
    gemm_kernel<<<(N + 63) / 64, 256, 96 * 1024>>>(h, W, attn, N);

    edge_pre<<<(E + 255) / 256, 256>>>(src, dst, E);

    long long thr = (long long)E * 32;
    edge_accum<<<(int)((thr + 255) / 256), 256>>>(src, dst, et, rel, out, E);

    finalize<<<(N * 32 + 255) / 256, 256>>>(out, N);
}